// round 1
// baseline (speedup 1.0000x reference)
#include <cuda_runtime.h>
#include <cuda_bf16.h>
#include <math.h>

// Problem constants
#define BATCH 2
#define SEQ   1024
#define DMODEL 1024
#define NHEAD 16
#define HEADD 64
#define NLAYER 3
#define FFDIM 4096
#define VOCAB 32000
#define MROWS (BATCH*SEQ)   // 2048

// ---------------- scratch (device globals: allocation-guard safe) -------------
__device__ float g_h  [MROWS*DMODEL];
__device__ float g_xn [MROWS*DMODEL];
__device__ float g_q  [MROWS*DMODEL];
__device__ float g_k  [MROWS*DMODEL];
__device__ float g_v  [MROWS*DMODEL];
__device__ float g_att[MROWS*DMODEL];
__device__ float g_ff [MROWS*FFDIM];
__device__ int   g_x_is64;

// ---------------- token dtype detection (int64 vs int32) ---------------------
// If tokens are int64 little-endian, the int32 view is (lo,hi) pairs with hi==0
// (tokens in [0,32000)). If int32, odd positions are random tokens -> ~surely
// at least one nonzero among 1024. Reads only the first ntok int32s (safe for
// either dtype).
__global__ void detect_kernel(const int* __restrict__ x32, int ntok) {
    __shared__ int ok;
    if (threadIdx.x == 0) ok = 1;
    __syncthreads();
    for (int i = threadIdx.x * 2 + 1; i < ntok; i += 2 * blockDim.x) {
        if (x32[i] != 0) { ok = 0; break; }
    }
    __syncthreads();
    if (threadIdx.x == 0) g_x_is64 = ok;
}

// ---------------- embedding: h = tok_emb[x] + pos_emb ------------------------
__global__ __launch_bounds__(256) void embed_kernel(
    const void* __restrict__ x,
    const float* __restrict__ tok_emb,
    const float* __restrict__ pos_emb)
{
    int row = blockIdx.x;           // 0..MROWS-1
    int s = row & (SEQ - 1);
    long long t;
    if (g_x_is64) t = ((const long long*)x)[row];
    else          t = (long long)(((const int*)x)[row]);
    const float4* te = (const float4*)(tok_emb + (size_t)t * DMODEL);
    const float4* pe = (const float4*)(pos_emb + (size_t)s * DMODEL);
    float4* out = (float4*)(g_h + (size_t)row * DMODEL);
    int i = threadIdx.x;            // 256 threads x float4 = 1024 floats
    float4 a = te[i], b = pe[i];
    out[i] = make_float4(a.x + b.x, a.y + b.y, a.z + b.z, a.w + b.w);
}

// ---------------- layernorm (one block per row, D=1024) ----------------------
__global__ __launch_bounds__(256) void ln_kernel(
    const float* __restrict__ x, const float* __restrict__ g,
    const float* __restrict__ b, float* __restrict__ y)
{
    int row = blockIdx.x;
    int tid = threadIdx.x;
    float4 val = ((const float4*)(x + (size_t)row * DMODEL))[tid];
    float s = val.x + val.y + val.z + val.w;
    float q = val.x*val.x + val.y*val.y + val.z*val.z + val.w*val.w;
    #pragma unroll
    for (int o = 16; o > 0; o >>= 1) {
        s += __shfl_xor_sync(0xffffffffu, s, o);
        q += __shfl_xor_sync(0xffffffffu, q, o);
    }
    __shared__ float sa[8], sb[8];
    __shared__ float s_mu, s_inv;
    int w = tid >> 5;
    if ((tid & 31) == 0) { sa[w] = s; sb[w] = q; }
    __syncthreads();
    if (tid == 0) {
        float ts = 0.f, tq = 0.f;
        #pragma unroll
        for (int i = 0; i < 8; i++) { ts += sa[i]; tq += sb[i]; }
        float mu = ts * (1.0f / DMODEL);
        float var = tq * (1.0f / DMODEL) - mu * mu;
        s_mu = mu;
        s_inv = rsqrtf(var + 1e-5f);
    }
    __syncthreads();
    float mu = s_mu, inv = s_inv;
    float4 gg = ((const float4*)g)[tid];
    float4 bb = ((const float4*)b)[tid];
    float4 out;
    out.x = (val.x - mu) * inv * gg.x + bb.x;
    out.y = (val.y - mu) * inv * gg.y + bb.y;
    out.z = (val.z - mu) * inv * gg.z + bb.z;
    out.w = (val.w - mu) * inv * gg.w + bb.w;
    ((float4*)(y + (size_t)row * DMODEL))[tid] = out;
}

// ---------------- SGEMM: C = A[M,K] @ B[K,N] + bias (+epilogue) --------------
// 128x128 block tile, K-step 8, 256 threads, 8x8 per thread.
// mode: 0 = store, 1 = exact GELU, 2 = residual add (C += result)
__global__ __launch_bounds__(256) void sgemm_kernel(
    int M, int N, int K,
    const float* __restrict__ A, const float* __restrict__ B,
    const float* __restrict__ bias, float* C, int mode)
{
    __shared__ float As[8][132];
    __shared__ float Bs[8][132];
    int tid = threadIdx.x;
    int trow = tid >> 4;            // 0..15
    int tcol = tid & 15;            // 0..15
    int bm = blockIdx.y * 128;
    int bn = blockIdx.x * 128;

    float acc[8][8];
    #pragma unroll
    for (int i = 0; i < 8; i++)
        #pragma unroll
        for (int j = 0; j < 8; j++) acc[i][j] = 0.f;

    int arow = tid >> 1;            // 0..127
    int acol = (tid & 1) * 4;       // 0 or 4
    int brow = tid >> 5;            // 0..7
    int bcol = (tid & 31) * 4;      // 0..124

    const float* Aptr = A + (size_t)(bm + arow) * K + acol;
    const float* Bptr = B + (size_t)brow * N + bn + bcol;

    for (int kt = 0; kt < K; kt += 8) {
        float4 a4 = *(const float4*)(Aptr + kt);
        As[acol + 0][arow] = a4.x;
        As[acol + 1][arow] = a4.y;
        As[acol + 2][arow] = a4.z;
        As[acol + 3][arow] = a4.w;
        *(float4*)&Bs[brow][bcol] = *(const float4*)(Bptr + (size_t)kt * N);
        __syncthreads();
        #pragma unroll
        for (int kk = 0; kk < 8; kk++) {
            float af[8], bf[8];
            #pragma unroll
            for (int i = 0; i < 8; i += 4)
                *(float4*)&af[i] = *(const float4*)&As[kk][trow * 8 + i];
            #pragma unroll
            for (int j = 0; j < 8; j += 4)
                *(float4*)&bf[j] = *(const float4*)&Bs[kk][tcol * 8 + j];
            #pragma unroll
            for (int i = 0; i < 8; i++)
                #pragma unroll
                for (int j = 0; j < 8; j++)
                    acc[i][j] = fmaf(af[i], bf[j], acc[i][j]);
        }
        __syncthreads();
    }

    float bf_[8];
    #pragma unroll
    for (int j = 0; j < 8; j++) bf_[j] = bias[bn + tcol * 8 + j];

    #pragma unroll
    for (int i = 0; i < 8; i++) {
        size_t row = (size_t)(bm + trow * 8 + i);
        float* crow = C + row * (size_t)N + bn + tcol * 8;
        #pragma unroll
        for (int j = 0; j < 8; j++) {
            float vv = acc[i][j] + bf_[j];
            if (mode == 1) {
                vv = 0.5f * vv * (1.0f + erff(vv * 0.70710678118654752f));
            } else if (mode == 2) {
                vv += crow[j];
            }
            crow[j] = vv;
        }
    }
}

// ---------------- causal flash attention -------------------------------------
// One thread = one query row (thread-local online softmax, no reductions).
// Block: 128 q rows; KV tiles of 32 in smem; scores staged in smem.
__global__ __launch_bounds__(128) void attn_kernel(
    const float* __restrict__ q, const float* __restrict__ k,
    const float* __restrict__ v, float* __restrict__ o_out)
{
    __shared__ float ks[32][64];
    __shared__ float vs[32][64];
    __shared__ float ss[32][128];
    int tid = threadIdx.x;
    int bx = blockIdx.x;            // q tile (128 rows each)
    int hh = blockIdx.y;
    int bb = blockIdx.z;
    int qi = bx * 128 + tid;        // query row within sequence
    size_t base = ((size_t)bb * SEQ) * DMODEL + (size_t)hh * HEADD;

    float qr[64], o[64];
    const float* qrow = q + base + (size_t)qi * DMODEL;
    #pragma unroll
    for (int d4 = 0; d4 < 64; d4 += 4) {
        float4 t = *(const float4*)(qrow + d4);
        qr[d4+0] = t.x * 0.125f; qr[d4+1] = t.y * 0.125f;
        qr[d4+2] = t.z * 0.125f; qr[d4+3] = t.w * 0.125f;
        o[d4+0] = 0.f; o[d4+1] = 0.f; o[d4+2] = 0.f; o[d4+3] = 0.f;
    }
    float m = -1e30f, l = 0.f;

    int ntiles = bx * 4 + 4;        // kv tiles needed for this q tile (causal)
    for (int kt = 0; kt < ntiles; kt++) {
        const float* kb = k + base + (size_t)(kt * 32) * DMODEL;
        const float* vb = v + base + (size_t)(kt * 32) * DMODEL;
        #pragma unroll
        for (int it = 0; it < 4; it++) {
            int idx = tid + it * 128;        // 512 float4s total
            int r = idx >> 4;
            int c = (idx & 15) << 2;
            *(float4*)&ks[r][c] = *(const float4*)(kb + (size_t)r * DMODEL + c);
            *(float4*)&vs[r][c] = *(const float4*)(vb + (size_t)r * DMODEL + c);
        }
        __syncthreads();
        int jmax = qi - kt * 32;
        if (jmax >= 0) {
            float tmax = -1e30f;
            for (int j = 0; j < 32; j++) {
                float acc = 0.f;
                #pragma unroll
                for (int d = 0; d < 64; d++) acc = fmaf(qr[d], ks[j][d], acc);
                if (j > jmax) acc = -1e30f;
                ss[j][tid] = acc;
                tmax = fmaxf(tmax, acc);
            }
            float mnew = fmaxf(m, tmax);
            float alpha = __expf(m - mnew);
            l *= alpha;
            #pragma unroll
            for (int d = 0; d < 64; d++) o[d] *= alpha;
            for (int j = 0; j < 32; j++) {
                float p = __expf(ss[j][tid] - mnew);
                l += p;
                #pragma unroll
                for (int d = 0; d < 64; d++) o[d] = fmaf(p, vs[j][d], o[d]);
            }
            m = mnew;
        }
        __syncthreads();
    }
    float inv = 1.0f / l;
    float* orow = o_out + base + (size_t)qi * DMODEL;
    #pragma unroll
    for (int d4 = 0; d4 < 64; d4 += 4) {
        float4 t;
        t.x = o[d4+0] * inv; t.y = o[d4+1] * inv;
        t.z = o[d4+2] * inv; t.w = o[d4+3] * inv;
        *(float4*)(orow + d4) = t;
    }
}

// ---------------- host orchestration -----------------------------------------
static inline void gemm(const float* A, const float* B, const float* bias,
                        float* C, int M, int N, int K, int mode) {
    dim3 grid(N / 128, M / 128);
    sgemm_kernel<<<grid, 256>>>(M, N, K, A, B, bias, C, mode);
}

extern "C" void kernel_launch(void* const* d_in, const int* in_sizes, int n_in,
                              void* d_out, int out_size)
{
    const void*  x       = d_in[0];
    const float* tok_emb = (const float*)d_in[1];
    const float* pos_emb = (const float*)d_in[2];
    const float* Wq = (const float*)d_in[3];
    const float* bq = (const float*)d_in[4];
    const float* Wk = (const float*)d_in[5];
    const float* bk = (const float*)d_in[6];
    const float* Wv = (const float*)d_in[7];
    const float* bv = (const float*)d_in[8];
    const float* Wo = (const float*)d_in[9];
    const float* bo = (const float*)d_in[10];
    const float* ln1_g = (const float*)d_in[11];
    const float* ln1_b = (const float*)d_in[12];
    const float* ln2_g = (const float*)d_in[13];
    const float* ln2_b = (const float*)d_in[14];
    const float* W1 = (const float*)d_in[15];
    const float* b1 = (const float*)d_in[16];
    const float* W2 = (const float*)d_in[17];
    const float* b2 = (const float*)d_in[18];
    const float* lnf_g = (const float*)d_in[19];
    const float* lnf_b = (const float*)d_in[20];
    const float* Wout = (const float*)d_in[21];
    const float* bout = (const float*)d_in[22];

    float *h, *xn, *q, *k, *v, *att, *ff;
    cudaGetSymbolAddress((void**)&h,   g_h);
    cudaGetSymbolAddress((void**)&xn,  g_xn);
    cudaGetSymbolAddress((void**)&q,   g_q);
    cudaGetSymbolAddress((void**)&k,   g_k);
    cudaGetSymbolAddress((void**)&v,   g_v);
    cudaGetSymbolAddress((void**)&att, g_att);
    cudaGetSymbolAddress((void**)&ff,  g_ff);

    const int M = MROWS, D = DMODEL, F = FFDIM;

    detect_kernel<<<1, 256>>>((const int*)x, M);
    embed_kernel<<<M, 256>>>(x, tok_emb, pos_emb);

    for (int i = 0; i < NLAYER; i++) {
        // attention block
        ln_kernel<<<M, 256>>>(h, ln1_g + (size_t)i * D, ln1_b + (size_t)i * D, xn);
        gemm(xn, Wq + (size_t)i * D * D, bq + (size_t)i * D, q, M, D, D, 0);
        gemm(xn, Wk + (size_t)i * D * D, bk + (size_t)i * D, k, M, D, D, 0);
        gemm(xn, Wv + (size_t)i * D * D, bv + (size_t)i * D, v, M, D, D, 0);
        attn_kernel<<<dim3(SEQ / 128, NHEAD, BATCH), 128>>>(q, k, v, att);
        gemm(att, Wo + (size_t)i * D * D, bo + (size_t)i * D, h, M, D, D, 2);
        // FFN block
        ln_kernel<<<M, 256>>>(h, ln2_g + (size_t)i * D, ln2_b + (size_t)i * D, xn);
        gemm(xn, W1 + (size_t)i * D * F, b1 + (size_t)i * F, ff, M, F, D, 1);
        gemm(ff, W2 + (size_t)i * F * D, b2 + (size_t)i * D, h, M, D, F, 2);
    }

    ln_kernel<<<M, 256>>>(h, lnf_g, lnf_b, xn);
    gemm(xn, Wout, bout, (float*)d_out, M, VOCAB, D, 0);
}

// round 7
// speedup vs baseline: 2.2034x; 2.2034x over previous
#include <cuda_runtime.h>
#include <cuda_bf16.h>
#include <math.h>
#include <stdint.h>

// Problem constants
#define BATCH 2
#define SEQ   1024
#define DMODEL 1024
#define NHEAD 16
#define HEADD 64
#define NLAYER 3
#define FFDIM 4096
#define VOCAB 32000
#define MROWS (BATCH*SEQ)   // 2048

// ---------------- scratch (device globals: allocation-guard safe) -------------
__device__ float g_h  [MROWS*DMODEL];
__device__ float g_xn [MROWS*DMODEL];
__device__ float g_q  [MROWS*DMODEL];
__device__ float g_k  [MROWS*DMODEL];
__device__ float g_v  [MROWS*DMODEL];
__device__ float g_att[MROWS*DMODEL];
__device__ float g_ff [MROWS*FFDIM];
__device__ int   g_x_is64;

// ---------------- token dtype detection (int64 vs int32) ---------------------
__global__ void detect_kernel(const int* __restrict__ x32, int ntok) {
    __shared__ int ok;
    if (threadIdx.x == 0) ok = 1;
    __syncthreads();
    for (int i = threadIdx.x * 2 + 1; i < ntok; i += 2 * blockDim.x) {
        if (x32[i] != 0) { ok = 0; break; }
    }
    __syncthreads();
    if (threadIdx.x == 0) g_x_is64 = ok;
}

// ---------------- embedding --------------------------------------------------
__global__ __launch_bounds__(256) void embed_kernel(
    const void* __restrict__ x,
    const float* __restrict__ tok_emb,
    const float* __restrict__ pos_emb)
{
    int row = blockIdx.x;
    int s = row & (SEQ - 1);
    long long t;
    if (g_x_is64) t = ((const long long*)x)[row];
    else          t = (long long)(((const int*)x)[row]);
    const float4* te = (const float4*)(tok_emb + (size_t)t * DMODEL);
    const float4* pe = (const float4*)(pos_emb + (size_t)s * DMODEL);
    float4* out = (float4*)(g_h + (size_t)row * DMODEL);
    int i = threadIdx.x;
    float4 a = te[i], b = pe[i];
    out[i] = make_float4(a.x + b.x, a.y + b.y, a.z + b.z, a.w + b.w);
}

// ---------------- layernorm --------------------------------------------------
__global__ __launch_bounds__(256) void ln_kernel(
    const float* __restrict__ x, const float* __restrict__ g,
    const float* __restrict__ b, float* __restrict__ y)
{
    int row = blockIdx.x;
    int tid = threadIdx.x;
    float4 val = ((const float4*)(x + (size_t)row * DMODEL))[tid];
    float s = val.x + val.y + val.z + val.w;
    float q = val.x*val.x + val.y*val.y + val.z*val.z + val.w*val.w;
    #pragma unroll
    for (int o = 16; o > 0; o >>= 1) {
        s += __shfl_xor_sync(0xffffffffu, s, o);
        q += __shfl_xor_sync(0xffffffffu, q, o);
    }
    __shared__ float sa[8], sb[8];
    __shared__ float s_mu, s_inv;
    int w = tid >> 5;
    if ((tid & 31) == 0) { sa[w] = s; sb[w] = q; }
    __syncthreads();
    if (tid == 0) {
        float ts = 0.f, tq = 0.f;
        #pragma unroll
        for (int i = 0; i < 8; i++) { ts += sa[i]; tq += sb[i]; }
        float mu = ts * (1.0f / DMODEL);
        float var = tq * (1.0f / DMODEL) - mu * mu;
        s_mu = mu;
        s_inv = rsqrtf(var + 1e-5f);
    }
    __syncthreads();
    float mu = s_mu, inv = s_inv;
    float4 gg = ((const float4*)g)[tid];
    float4 bb = ((const float4*)b)[tid];
    float4 out;
    out.x = (val.x - mu) * inv * gg.x + bb.x;
    out.y = (val.y - mu) * inv * gg.y + bb.y;
    out.z = (val.z - mu) * inv * gg.z + bb.z;
    out.w = (val.w - mu) * inv * gg.w + bb.w;
    ((float4*)(y + (size_t)row * DMODEL))[tid] = out;
}

// ============================================================================
// bf16 split GEMM via mma.sync (m16n8k16):
//   C[M,N] = A[M,K] @ W[K,N] + bias (+epilogue)
//   v = hi + lo (hi = trunc-bf16);  D = AhiBhi + AhiBlo + AloBhi
// Block 128x128, 8 warps (4m x 2n), warp tile 32x64, K-chunk 32, double-buffer.
// smem per stage: A(hi,lo) + B(hi,lo), rows padded to 40 halves (80B) each.
// ============================================================================

#define ROWB      80          // padded row stride in bytes (40 halves)
#define TILE_B    10240       // 128 rows * 80B (one hi or lo tile)
#define STAGE_B   40960       // Ahi, Alo, Bhi, Blo
#define GEMM_SMEM (2*STAGE_B) // 81920

__device__ __forceinline__ uint32_t smem_u32(const void* p) {
    uint32_t a;
    asm("{ .reg .u64 t; cvta.to.shared.u64 t, %1; cvt.u32.u64 %0, t; }" : "=r"(a) : "l"(p));
    return a;
}
// hi = trunc-to-bf16 pair, lo = rn-bf16(v - hi) pair
__device__ __forceinline__ void split2(float vx, float vy, uint32_t& hi, uint32_t& lo) {
    uint32_t ux = __float_as_uint(vx);
    uint32_t uy = __float_as_uint(vy);
    hi = __byte_perm(ux, uy, 0x7632);
    float lx = vx - __uint_as_float(ux & 0xFFFF0000u);
    float ly = vy - __uint_as_float(uy & 0xFFFF0000u);
    asm("cvt.rn.bf16x2.f32 %0, %1, %2;" : "=r"(lo) : "f"(ly), "f"(lx));
}
__device__ __forceinline__ void ldsm4(uint32_t* r, uint32_t addr) {
    asm volatile("ldmatrix.sync.aligned.m8n8.x4.shared.b16 {%0,%1,%2,%3}, [%4];"
                 : "=r"(r[0]), "=r"(r[1]), "=r"(r[2]), "=r"(r[3]) : "r"(addr));
}
__device__ __forceinline__ void mma16816(float* c, const uint32_t* a, const uint32_t* b) {
    asm volatile(
        "mma.sync.aligned.m16n8k16.row.col.f32.bf16.bf16.f32 "
        "{%0,%1,%2,%3}, {%4,%5,%6,%7}, {%8,%9}, {%0,%1,%2,%3};"
        : "+f"(c[0]), "+f"(c[1]), "+f"(c[2]), "+f"(c[3])
        : "r"(a[0]), "r"(a[1]), "r"(a[2]), "r"(a[3]), "r"(b[0]), "r"(b[1]));
}

__global__ __launch_bounds__(256, 1) void tgemm_kernel(
    int M, int N, int K,
    const float* __restrict__ A, const float* __restrict__ W,
    const float* __restrict__ bias, float* C, int mode)
{
    extern __shared__ char smem[];
    uint32_t sb = smem_u32(smem);
    int tid = threadIdx.x;
    int wid = tid >> 5;
    int lane = tid & 31;
    int bm = blockIdx.y * 128;
    int bn = blockIdx.x * 128;

    // ---- per-thread global load coords ----
    // A: m = tid>>1 (0..127), k-quarter = (tid&1)*16
    int am = tid >> 1;
    int ak = (tid & 1) * 16;
    const float* Ap = A + (size_t)(bm + am) * K + ak;
    // B: n = tid&127, k-group = (tid>>7)*16
    int bnn = tid & 127;
    int bkg = (tid >> 7) * 16;
    const float* Wp = W + (size_t)bkg * N + bn + bnn;

    float ar[16], br[16];

    // ---- smem stage pointers ----
    char* st[2] = { smem, smem + STAGE_B };

    // ---- accumulators ----
    float acc[2][8][4];
    #pragma unroll
    for (int i = 0; i < 2; i++)
        #pragma unroll
        for (int j = 0; j < 8; j++)
            #pragma unroll
            for (int q = 0; q < 4; q++) acc[i][j][q] = 0.f;

    const int KT = K >> 5;   // chunks of 32

    // ---- warp/lane fragment addresses (byte offsets within a tile) ----
    int wm = wid & 3;        // m warp: 32*wm
    int wn = wid >> 2;       // n warp: 64*wn
    int g  = lane >> 3;      // ldmatrix lane-group
    int lr = lane & 7;
    // A: row = wm*32 + mt*16 + (g&1)*8 + lr ; col8 = (g>>1)*8 (+ks*16)
    uint32_t a_off = (uint32_t)((wm * 32 + (g & 1) * 8 + lr) * ROWB + ((g >> 1) * 8) * 2);
    // B: row = wn*64 + nt2*16 + (g>>1)*8 + lr ; col8 = (g&1)*8 (+ks*16)
    uint32_t b_off = (uint32_t)((wn * 64 + (g >> 1) * 8 + lr) * ROWB + ((g & 1) * 8) * 2);

    // ================= helpers as macros (keep regs local) ==================
#define LOAD_CHUNK(kt) do {                                                   \
        const float* ap_ = Ap + (kt) * 32;                                    \
        float4 v0 = *(const float4*)(ap_);                                    \
        float4 v1 = *(const float4*)(ap_ + 4);                                \
        float4 v2 = *(const float4*)(ap_ + 8);                                \
        float4 v3 = *(const float4*)(ap_ + 12);                               \
        ar[0]=v0.x; ar[1]=v0.y; ar[2]=v0.z; ar[3]=v0.w;                       \
        ar[4]=v1.x; ar[5]=v1.y; ar[6]=v1.z; ar[7]=v1.w;                       \
        ar[8]=v2.x; ar[9]=v2.y; ar[10]=v2.z; ar[11]=v2.w;                     \
        ar[12]=v3.x; ar[13]=v3.y; ar[14]=v3.z; ar[15]=v3.w;                   \
        const float* wp_ = Wp + (size_t)(kt) * 32 * N;                        \
        _Pragma("unroll")                                                     \
        for (int t = 0; t < 16; t++) br[t] = wp_[(size_t)t * N];              \
    } while (0)

#define STORE_CHUNK(s) do {                                                   \
        char* base_ = st[s];                                                  \
        uint32_t h[8], l[8];                                                  \
        _Pragma("unroll")                                                     \
        for (int t = 0; t < 8; t++) split2(ar[2*t], ar[2*t+1], h[t], l[t]);   \
        {                                                                     \
            char* p = base_ + am * ROWB + ak * 2;                             \
            *(uint4*)(p)                = make_uint4(h[0],h[1],h[2],h[3]);    \
            *(uint4*)(p + 16)           = make_uint4(h[4],h[5],h[6],h[7]);    \
            *(uint4*)(p + TILE_B)       = make_uint4(l[0],l[1],l[2],l[3]);    \
            *(uint4*)(p + TILE_B + 16)  = make_uint4(l[4],l[5],l[6],l[7]);    \
        }                                                                     \
        _Pragma("unroll")                                                     \
        for (int t = 0; t < 8; t++) split2(br[2*t], br[2*t+1], h[t], l[t]);   \
        {                                                                     \
            char* p = base_ + 2*TILE_B + bnn * ROWB + bkg * 2;                \
            *(uint4*)(p)                = make_uint4(h[0],h[1],h[2],h[3]);    \
            *(uint4*)(p + 16)           = make_uint4(h[4],h[5],h[6],h[7]);    \
            *(uint4*)(p + TILE_B)       = make_uint4(l[0],l[1],l[2],l[3]);    \
            *(uint4*)(p + TILE_B + 16)  = make_uint4(l[4],l[5],l[6],l[7]);    \
        }                                                                     \
    } while (0)

    // ---- preload chunk 0 ----
    LOAD_CHUNK(0);
    STORE_CHUNK(0);
    __syncthreads();

    for (int kt = 0; kt < KT; kt++) {
        int s = kt & 1;
        if (kt + 1 < KT) LOAD_CHUNK(kt + 1);

        uint32_t sA = sb + s * STAGE_B + a_off;
        uint32_t sB = sb + s * STAGE_B + 2 * TILE_B + b_off;

        #pragma unroll
        for (int ks = 0; ks < 2; ks++) {
            uint32_t ah[2][4], al[2][4];
            uint32_t bh[8][2], bl[8][2];
            #pragma unroll
            for (int mt = 0; mt < 2; mt++) {
                uint32_t addr = sA + mt * 16 * ROWB + ks * 32;
                ldsm4(ah[mt], addr);
                ldsm4(al[mt], addr + TILE_B);
            }
            #pragma unroll
            for (int nt2 = 0; nt2 < 4; nt2++) {
                uint32_t addr = sB + nt2 * 16 * ROWB + ks * 32;
                uint32_t r[4];
                ldsm4(r, addr);
                bh[nt2*2][0] = r[0]; bh[nt2*2][1] = r[1];
                bh[nt2*2+1][0] = r[2]; bh[nt2*2+1][1] = r[3];
                ldsm4(r, addr + TILE_B);
                bl[nt2*2][0] = r[0]; bl[nt2*2][1] = r[1];
                bl[nt2*2+1][0] = r[2]; bl[nt2*2+1][1] = r[3];
            }
            #pragma unroll
            for (int mt = 0; mt < 2; mt++)
                #pragma unroll
                for (int nt = 0; nt < 8; nt++) {
                    mma16816(acc[mt][nt], ah[mt], bh[nt]);
                    mma16816(acc[mt][nt], ah[mt], bl[nt]);
                    mma16816(acc[mt][nt], al[mt], bh[nt]);
                }
        }

        if (kt + 1 < KT) {
            __syncthreads();
            STORE_CHUNK((kt + 1) & 1);
            __syncthreads();
        }
    }

    // ---- epilogue --------------------------------------------------------
    int r0 = lane >> 2;
    int cc = (lane & 3) * 2;
    #pragma unroll
    for (int mt = 0; mt < 2; mt++) {
        int m0 = bm + wm * 32 + mt * 16 + r0;
        #pragma unroll
        for (int nt = 0; nt < 8; nt++) {
            int n0 = bn + wn * 64 + nt * 8 + cc;
            float b0 = bias[n0], b1 = bias[n0 + 1];
            #pragma unroll
            for (int half = 0; half < 2; half++) {
                int m = m0 + half * 8;
                float vx = acc[mt][nt][half*2 + 0] + b0;
                float vy = acc[mt][nt][half*2 + 1] + b1;
                float* cp = C + (size_t)m * N + n0;
                if (mode == 1) {
                    vx = 0.5f * vx * (1.0f + erff(vx * 0.70710678118654752f));
                    vy = 0.5f * vy * (1.0f + erff(vy * 0.70710678118654752f));
                } else if (mode == 2) {
                    float2 old = *(float2*)cp;
                    vx += old.x; vy += old.y;
                }
                *(float2*)cp = make_float2(vx, vy);
            }
        }
    }
#undef LOAD_CHUNK
#undef STORE_CHUNK
}

// ---------------- causal flash attention (fp32) -------------------------------
__global__ __launch_bounds__(128) void attn_kernel(
    const float* __restrict__ q, const float* __restrict__ k,
    const float* __restrict__ v, float* __restrict__ o_out)
{
    __shared__ float ks[32][64];
    __shared__ float vs[32][64];
    __shared__ float ss[32][128];
    int tid = threadIdx.x;
    int bx = blockIdx.x;
    int hh = blockIdx.y;
    int bb = blockIdx.z;
    int qi = bx * 128 + tid;
    size_t base = ((size_t)bb * SEQ) * DMODEL + (size_t)hh * HEADD;

    float qr[64], o[64];
    const float* qrow = q + base + (size_t)qi * DMODEL;
    #pragma unroll
    for (int d4 = 0; d4 < 64; d4 += 4) {
        float4 t = *(const float4*)(qrow + d4);
        qr[d4+0] = t.x * 0.125f; qr[d4+1] = t.y * 0.125f;
        qr[d4+2] = t.z * 0.125f; qr[d4+3] = t.w * 0.125f;
        o[d4+0] = 0.f; o[d4+1] = 0.f; o[d4+2] = 0.f; o[d4+3] = 0.f;
    }
    float m = -1e30f, l = 0.f;

    int ntiles = bx * 4 + 4;
    for (int kt = 0; kt < ntiles; kt++) {
        const float* kb = k + base + (size_t)(kt * 32) * DMODEL;
        const float* vb = v + base + (size_t)(kt * 32) * DMODEL;
        #pragma unroll
        for (int it = 0; it < 4; it++) {
            int idx = tid + it * 128;
            int r = idx >> 4;
            int c = (idx & 15) << 2;
            *(float4*)&ks[r][c] = *(const float4*)(kb + (size_t)r * DMODEL + c);
            *(float4*)&vs[r][c] = *(const float4*)(vb + (size_t)r * DMODEL + c);
        }
        __syncthreads();
        int jmax = qi - kt * 32;
        if (jmax >= 0) {
            float tmax = -1e30f;
            for (int j = 0; j < 32; j++) {
                float acc = 0.f;
                #pragma unroll
                for (int d = 0; d < 64; d++) acc = fmaf(qr[d], ks[j][d], acc);
                if (j > jmax) acc = -1e30f;
                ss[j][tid] = acc;
                tmax = fmaxf(tmax, acc);
            }
            float mnew = fmaxf(m, tmax);
            float alpha = __expf(m - mnew);
            l *= alpha;
            #pragma unroll
            for (int d = 0; d < 64; d++) o[d] *= alpha;
            for (int j = 0; j < 32; j++) {
                float p = __expf(ss[j][tid] - mnew);
                l += p;
                #pragma unroll
                for (int d = 0; d < 64; d++) o[d] = fmaf(p, vs[j][d], o[d]);
            }
            m = mnew;
        }
        __syncthreads();
    }
    float inv = 1.0f / l;
    float* orow = o_out + base + (size_t)qi * DMODEL;
    #pragma unroll
    for (int d4 = 0; d4 < 64; d4 += 4) {
        float4 t;
        t.x = o[d4+0] * inv; t.y = o[d4+1] * inv;
        t.z = o[d4+2] * inv; t.w = o[d4+3] * inv;
        *(float4*)(orow + d4) = t;
    }
}

// ---------------- host orchestration -----------------------------------------
static inline void tgemm(const float* A, const float* W, const float* bias,
                         float* C, int M, int N, int K, int mode) {
    dim3 grid(N / 128, M / 128);
    tgemm_kernel<<<grid, 256, GEMM_SMEM>>>(M, N, K, A, W, bias, C, mode);
}

extern "C" void kernel_launch(void* const* d_in, const int* in_sizes, int n_in,
                              void* d_out, int out_size)
{
    const void*  x       = d_in[0];
    const float* tok_emb = (const float*)d_in[1];
    const float* pos_emb = (const float*)d_in[2];
    const float* Wq = (const float*)d_in[3];
    const float* bq = (const float*)d_in[4];
    const float* Wk = (const float*)d_in[5];
    const float* bk = (const float*)d_in[6];
    const float* Wv = (const float*)d_in[7];
    const float* bv = (const float*)d_in[8];
    const float* Wo = (const float*)d_in[9];
    const float* bo = (const float*)d_in[10];
    const float* ln1_g = (const float*)d_in[11];
    const float* ln1_b = (const float*)d_in[12];
    const float* ln2_g = (const float*)d_in[13];
    const float* ln2_b = (const float*)d_in[14];
    const float* W1 = (const float*)d_in[15];
    const float* b1 = (const float*)d_in[16];
    const float* W2 = (const float*)d_in[17];
    const float* b2 = (const float*)d_in[18];
    const float* lnf_g = (const float*)d_in[19];
    const float* lnf_b = (const float*)d_in[20];
    const float* Wout = (const float*)d_in[21];
    const float* bout = (const float*)d_in[22];

    float *h, *xn, *q, *k, *v, *att, *ff;
    cudaGetSymbolAddress((void**)&h,   g_h);
    cudaGetSymbolAddress((void**)&xn,  g_xn);
    cudaGetSymbolAddress((void**)&q,   g_q);
    cudaGetSymbolAddress((void**)&k,   g_k);
    cudaGetSymbolAddress((void**)&v,   g_v);
    cudaGetSymbolAddress((void**)&att, g_att);
    cudaGetSymbolAddress((void**)&ff,  g_ff);

    cudaFuncSetAttribute(tgemm_kernel,
                         cudaFuncAttributeMaxDynamicSharedMemorySize, GEMM_SMEM);

    const int M = MROWS, D = DMODEL, F = FFDIM;

    detect_kernel<<<1, 256>>>((const int*)x, M);
    embed_kernel<<<M, 256>>>(x, tok_emb, pos_emb);

    for (int i = 0; i < NLAYER; i++) {
        ln_kernel<<<M, 256>>>(h, ln1_g + (size_t)i * D, ln1_b + (size_t)i * D, xn);
        tgemm(xn, Wq + (size_t)i * D * D, bq + (size_t)i * D, q, M, D, D, 0);
        tgemm(xn, Wk + (size_t)i * D * D, bk + (size_t)i * D, k, M, D, D, 0);
        tgemm(xn, Wv + (size_t)i * D * D, bv + (size_t)i * D, v, M, D, D, 0);
        attn_kernel<<<dim3(SEQ / 128, NHEAD, BATCH), 128>>>(q, k, v, att);
        tgemm(att, Wo + (size_t)i * D * D, bo + (size_t)i * D, h, M, D, D, 2);
        ln_kernel<<<M, 256>>>(h, ln2_g + (size_t)i * D, ln2_b + (size_t)i * D, xn);
        tgemm(xn, W1 + (size_t)i * D * F, b1 + (size_t)i * F, ff, M, F, D, 1);
        tgemm(ff, W2 + (size_t)i * F * D, b2 + (size_t)i * D, h, M, D, F, 2);
    }

    ln_kernel<<<M, 256>>>(h, lnf_g, lnf_b, xn);
    tgemm(xn, Wout, bout, (float*)d_out, M, VOCAB, D, 0);
}